// round 2
// baseline (speedup 1.0000x reference)
#include <cuda_runtime.h>
#include <math.h>

#define DIM   1024
#define NPAT  8192
#define NROWS 8192   // B*S = 2*4096

// ---------------- scratch (allocation-free: __device__ global) ----------------
__device__ float g_q[NROWS * DIM];   // 32 MB: q = x @ w_q^T

// =============================================================================
// Kernel 1: q = x @ w_q^T   (both operands row-major, K contiguous -> "NT" GEMM)
// 128x128 tile, BK=8, 256 threads, 8x8 micro-tile per thread.
// =============================================================================
__global__ __launch_bounds__(256) void qgemm_kernel(const float* __restrict__ x,
                                                    const float* __restrict__ wq) {
    __shared__ float As[8][128];
    __shared__ float Bs[8][128];

    const int tid = threadIdx.x;
    const int tx  = tid & 15;          // 0..15 -> n
    const int ty  = tid >> 4;          // 0..15 -> m
    const int bm  = blockIdx.y * 128;
    const int bn  = blockIdx.x * 128;

    const int lrow = tid >> 1;         // 0..127
    const int lk4  = (tid & 1) * 4;    // 0 or 4

    float acc[8][8];
#pragma unroll
    for (int i = 0; i < 8; i++)
#pragma unroll
        for (int j = 0; j < 8; j++) acc[i][j] = 0.f;

    for (int k0 = 0; k0 < DIM; k0 += 8) {
        float4 av = *(const float4*)&x [(size_t)(bm + lrow) * DIM + k0 + lk4];
        float4 bv = *(const float4*)&wq[(size_t)(bn + lrow) * DIM + k0 + lk4];

        __syncthreads();
        As[lk4 + 0][lrow] = av.x; As[lk4 + 1][lrow] = av.y;
        As[lk4 + 2][lrow] = av.z; As[lk4 + 3][lrow] = av.w;
        Bs[lk4 + 0][lrow] = bv.x; Bs[lk4 + 1][lrow] = bv.y;
        Bs[lk4 + 2][lrow] = bv.z; Bs[lk4 + 3][lrow] = bv.w;
        __syncthreads();

#pragma unroll
        for (int k = 0; k < 8; k++) {
            float4 a0 = *(const float4*)&As[k][ty * 8];
            float4 a1 = *(const float4*)&As[k][ty * 8 + 4];
            float4 b0 = *(const float4*)&Bs[k][tx * 8];
            float4 b1 = *(const float4*)&Bs[k][tx * 8 + 4];
            float am[8] = {a0.x, a0.y, a0.z, a0.w, a1.x, a1.y, a1.z, a1.w};
            float bn_[8] = {b0.x, b0.y, b0.z, b0.w, b1.x, b1.y, b1.z, b1.w};
#pragma unroll
            for (int i = 0; i < 8; i++)
#pragma unroll
                for (int j = 0; j < 8; j++) acc[i][j] += am[i] * bn_[j];
        }
    }

#pragma unroll
    for (int i = 0; i < 8; i++) {
        float* dst = &g_q[(size_t)(bm + ty * 8 + i) * DIM + bn + tx * 8];
        float4 r0 = make_float4(acc[i][0], acc[i][1], acc[i][2], acc[i][3]);
        float4 r1 = make_float4(acc[i][4], acc[i][5], acc[i][6], acc[i][7]);
        *(float4*)(dst)     = r0;
        *(float4*)(dst + 4) = r1;
    }
}

// =============================================================================
// Kernel 2: fused  logits -> online softmax -> attn @ xi
// 256 threads = 8 warps; each warp owns 2 query rows (q + O accumulator in
// registers, lane d-slice = 4*lane + 128*i). xi streamed via smem in chunks of
// KP=16 patterns (64 KB dynamic smem). Online (flash) softmax per chunk.
// =============================================================================
#define KP     16
#define WARPS2 8
#define RPW    2
#define ROWS_PER_BLK (WARPS2 * RPW)   // 16

__global__ __launch_bounds__(256, 1) void hopfield_attn_kernel(
        const float* __restrict__ xi,
        const float* __restrict__ beta_p,
        float* __restrict__ out) {
    extern __shared__ float xs[];  // KP * DIM floats

    const float beta = *beta_p;
    const int tid  = threadIdx.x;
    const int lane = tid & 31;
    const int warp = tid >> 5;
    const size_t row0 = (size_t)blockIdx.x * ROWS_PER_BLK + warp * RPW;
    const size_t row1 = row0 + 1;

    // q rows in registers: lane holds dims {4*lane + 128*i}, i=0..7
    float4 q0[8], q1[8], o0[8], o1[8];
#pragma unroll
    for (int i = 0; i < 8; i++) {
        q0[i] = *(const float4*)&g_q[row0 * DIM + 4 * lane + 128 * i];
        q1[i] = *(const float4*)&g_q[row1 * DIM + 4 * lane + 128 * i];
        o0[i] = make_float4(0.f, 0.f, 0.f, 0.f);
        o1[i] = make_float4(0.f, 0.f, 0.f, 0.f);
    }
    float m0 = -INFINITY, m1 = -INFINITY, l0 = 0.f, l1 = 0.f;

    for (int c = 0; c < NPAT / KP; c++) {
        __syncthreads();
        // cooperative chunk load: KP*DIM floats = 4096 float4 / 256 threads
        {
            const float4* src = (const float4*)&xi[(size_t)c * KP * DIM];
            float4* dst = (float4*)xs;
#pragma unroll
            for (int t = 0; t < (KP * DIM / 4) / 256; t++)
                dst[tid + t * 256] = src[tid + t * 256];
        }
        __syncthreads();

        // ---- dot pass: s[p] = beta * <q, xi_p> ----
        float s0[KP], s1[KP];
#pragma unroll 1
        for (int p = 0; p < KP; p++) {
            const float4* xr = (const float4*)&xs[p * DIM];
            float a0 = 0.f, a1 = 0.f;
#pragma unroll
            for (int i = 0; i < 8; i++) {
                float4 v = xr[lane + 32 * i];
                a0 += q0[i].x * v.x + q0[i].y * v.y + q0[i].z * v.z + q0[i].w * v.w;
                a1 += q1[i].x * v.x + q1[i].y * v.y + q1[i].z * v.z + q1[i].w * v.w;
            }
#pragma unroll
            for (int off = 16; off > 0; off >>= 1) {
                a0 += __shfl_xor_sync(0xffffffffu, a0, off);
                a1 += __shfl_xor_sync(0xffffffffu, a1, off);
            }
            s0[p] = a0 * beta;
            s1[p] = a1 * beta;
        }

        // ---- online softmax rescale (once per chunk) ----
        float cm0 = s0[0], cm1 = s1[0];
#pragma unroll
        for (int p = 1; p < KP; p++) { cm0 = fmaxf(cm0, s0[p]); cm1 = fmaxf(cm1, s1[p]); }
        float nm0 = fmaxf(m0, cm0), nm1 = fmaxf(m1, cm1);
        float sc0 = __expf(m0 - nm0), sc1 = __expf(m1 - nm1);
        m0 = nm0; m1 = nm1;
        l0 *= sc0; l1 *= sc1;
#pragma unroll
        for (int i = 0; i < 8; i++) {
            o0[i].x *= sc0; o0[i].y *= sc0; o0[i].z *= sc0; o0[i].w *= sc0;
            o1[i].x *= sc1; o1[i].y *= sc1; o1[i].z *= sc1; o1[i].w *= sc1;
        }

        // ---- accumulate pass: O += exp(s - m) * xi_p ----
#pragma unroll 1
        for (int p = 0; p < KP; p++) {
            float w0 = __expf(s0[p] - m0);
            float w1 = __expf(s1[p] - m1);
            l0 += w0; l1 += w1;
            const float4* xr = (const float4*)&xs[p * DIM];
#pragma unroll
            for (int i = 0; i < 8; i++) {
                float4 v = xr[lane + 32 * i];
                o0[i].x += w0 * v.x; o0[i].y += w0 * v.y;
                o0[i].z += w0 * v.z; o0[i].w += w0 * v.w;
                o1[i].x += w1 * v.x; o1[i].y += w1 * v.y;
                o1[i].z += w1 * v.z; o1[i].w += w1 * v.w;
            }
        }
    }

    const float inv0 = 1.f / l0, inv1 = 1.f / l1;
#pragma unroll
    for (int i = 0; i < 8; i++) {
        float4 r0 = make_float4(o0[i].x * inv0, o0[i].y * inv0, o0[i].z * inv0, o0[i].w * inv0);
        float4 r1 = make_float4(o1[i].x * inv1, o1[i].y * inv1, o1[i].z * inv1, o1[i].w * inv1);
        *(float4*)&out[row0 * DIM + 4 * lane + 128 * i] = r0;
        *(float4*)&out[row1 * DIM + 4 * lane + 128 * i] = r1;
    }
}

// =============================================================================
// launch
// =============================================================================
extern "C" void kernel_launch(void* const* d_in, const int* in_sizes, int n_in,
                              void* d_out, int out_size) {
    const float* x    = (const float*)d_in[0];
    const float* wq   = (const float*)d_in[1];
    const float* xi   = (const float*)d_in[2];
    const float* beta = (const float*)d_in[3];
    float* out = (float*)d_out;

    dim3 g1(DIM / 128, NROWS / 128);  // (8, 64)
    qgemm_kernel<<<g1, 256>>>(x, wq);

    const int smem2 = KP * DIM * sizeof(float);  // 64 KB
    cudaFuncSetAttribute(hopfield_attn_kernel,
                         cudaFuncAttributeMaxDynamicSharedMemorySize, smem2);
    hopfield_attn_kernel<<<NROWS / ROWS_PER_BLK, 256, smem2>>>(xi, beta, out);
}

// round 3
// speedup vs baseline: 1.0007x; 1.0007x over previous
#include <cuda_runtime.h>
#include <math.h>

#define DIM   1024
#define NPAT  8192
#define NROWS 8192   // B*S = 2*4096

// ---------------- scratch (allocation-free: __device__ global) ----------------
__device__ float g_q[NROWS * DIM];   // 32 MB: q = x @ w_q^T

// =============================================================================
// Kernel 1: q = x @ w_q^T   (both operands row-major, K contiguous -> "NT" GEMM)
// 128x128 tile, BK=8, 256 threads, 8x8 micro-tile per thread.
// =============================================================================
__global__ __launch_bounds__(256) void qgemm_kernel(const float* __restrict__ x,
                                                    const float* __restrict__ wq) {
    __shared__ float As[8][128];
    __shared__ float Bs[8][128];

    const int tid = threadIdx.x;
    const int tx  = tid & 15;          // 0..15 -> n
    const int ty  = tid >> 4;          // 0..15 -> m
    const int bm  = blockIdx.y * 128;
    const int bn  = blockIdx.x * 128;

    const int lrow = tid >> 1;         // 0..127
    const int lk4  = (tid & 1) * 4;    // 0 or 4

    float acc[8][8];
#pragma unroll
    for (int i = 0; i < 8; i++)
#pragma unroll
        for (int j = 0; j < 8; j++) acc[i][j] = 0.f;

    for (int k0 = 0; k0 < DIM; k0 += 8) {
        float4 av = *(const float4*)&x [(size_t)(bm + lrow) * DIM + k0 + lk4];
        float4 bv = *(const float4*)&wq[(size_t)(bn + lrow) * DIM + k0 + lk4];

        __syncthreads();
        As[lk4 + 0][lrow] = av.x; As[lk4 + 1][lrow] = av.y;
        As[lk4 + 2][lrow] = av.z; As[lk4 + 3][lrow] = av.w;
        Bs[lk4 + 0][lrow] = bv.x; Bs[lk4 + 1][lrow] = bv.y;
        Bs[lk4 + 2][lrow] = bv.z; Bs[lk4 + 3][lrow] = bv.w;
        __syncthreads();

#pragma unroll
        for (int k = 0; k < 8; k++) {
            float4 a0 = *(const float4*)&As[k][ty * 8];
            float4 a1 = *(const float4*)&As[k][ty * 8 + 4];
            float4 b0 = *(const float4*)&Bs[k][tx * 8];
            float4 b1 = *(const float4*)&Bs[k][tx * 8 + 4];
            float am[8] = {a0.x, a0.y, a0.z, a0.w, a1.x, a1.y, a1.z, a1.w};
            float bn_[8] = {b0.x, b0.y, b0.z, b0.w, b1.x, b1.y, b1.z, b1.w};
#pragma unroll
            for (int i = 0; i < 8; i++)
#pragma unroll
                for (int j = 0; j < 8; j++) acc[i][j] += am[i] * bn_[j];
        }
    }

#pragma unroll
    for (int i = 0; i < 8; i++) {
        float* dst = &g_q[(size_t)(bm + ty * 8 + i) * DIM + bn + tx * 8];
        float4 r0 = make_float4(acc[i][0], acc[i][1], acc[i][2], acc[i][3]);
        float4 r1 = make_float4(acc[i][4], acc[i][5], acc[i][6], acc[i][7]);
        *(float4*)(dst)     = r0;
        *(float4*)(dst + 4) = r1;
    }
}

// =============================================================================
// Kernel 2: fused  logits -> online softmax -> attn @ xi
// 256 threads = 8 warps; each warp owns 2 query rows (q + O accumulator in
// registers, lane d-slice = 4*lane + 128*i). xi streamed via smem in chunks of
// KP=16 patterns (64 KB dynamic smem). Online (flash) softmax per chunk.
// =============================================================================
#define KP     16
#define WARPS2 8
#define RPW    2
#define ROWS_PER_BLK (WARPS2 * RPW)   // 16

__global__ __launch_bounds__(256, 1) void hopfield_attn_kernel(
        const float* __restrict__ xi,
        const float* __restrict__ beta_p,
        float* __restrict__ out) {
    extern __shared__ float xs[];  // KP * DIM floats

    const float beta = *beta_p;
    const int tid  = threadIdx.x;
    const int lane = tid & 31;
    const int warp = tid >> 5;
    const size_t row0 = (size_t)blockIdx.x * ROWS_PER_BLK + warp * RPW;
    const size_t row1 = row0 + 1;

    // q rows in registers: lane holds dims {4*lane + 128*i}, i=0..7
    float4 q0[8], q1[8], o0[8], o1[8];
#pragma unroll
    for (int i = 0; i < 8; i++) {
        q0[i] = *(const float4*)&g_q[row0 * DIM + 4 * lane + 128 * i];
        q1[i] = *(const float4*)&g_q[row1 * DIM + 4 * lane + 128 * i];
        o0[i] = make_float4(0.f, 0.f, 0.f, 0.f);
        o1[i] = make_float4(0.f, 0.f, 0.f, 0.f);
    }
    float m0 = -INFINITY, m1 = -INFINITY, l0 = 0.f, l1 = 0.f;

    for (int c = 0; c < NPAT / KP; c++) {
        __syncthreads();
        // cooperative chunk load: KP*DIM floats = 4096 float4 / 256 threads
        {
            const float4* src = (const float4*)&xi[(size_t)c * KP * DIM];
            float4* dst = (float4*)xs;
#pragma unroll
            for (int t = 0; t < (KP * DIM / 4) / 256; t++)
                dst[tid + t * 256] = src[tid + t * 256];
        }
        __syncthreads();

        // ---- dot pass: s[p] = beta * <q, xi_p> ----
        float s0[KP], s1[KP];
#pragma unroll 1
        for (int p = 0; p < KP; p++) {
            const float4* xr = (const float4*)&xs[p * DIM];
            float a0 = 0.f, a1 = 0.f;
#pragma unroll
            for (int i = 0; i < 8; i++) {
                float4 v = xr[lane + 32 * i];
                a0 += q0[i].x * v.x + q0[i].y * v.y + q0[i].z * v.z + q0[i].w * v.w;
                a1 += q1[i].x * v.x + q1[i].y * v.y + q1[i].z * v.z + q1[i].w * v.w;
            }
#pragma unroll
            for (int off = 16; off > 0; off >>= 1) {
                a0 += __shfl_xor_sync(0xffffffffu, a0, off);
                a1 += __shfl_xor_sync(0xffffffffu, a1, off);
            }
            s0[p] = a0 * beta;
            s1[p] = a1 * beta;
        }

        // ---- online softmax rescale (once per chunk) ----
        float cm0 = s0[0], cm1 = s1[0];
#pragma unroll
        for (int p = 1; p < KP; p++) { cm0 = fmaxf(cm0, s0[p]); cm1 = fmaxf(cm1, s1[p]); }
        float nm0 = fmaxf(m0, cm0), nm1 = fmaxf(m1, cm1);
        float sc0 = __expf(m0 - nm0), sc1 = __expf(m1 - nm1);
        m0 = nm0; m1 = nm1;
        l0 *= sc0; l1 *= sc1;
#pragma unroll
        for (int i = 0; i < 8; i++) {
            o0[i].x *= sc0; o0[i].y *= sc0; o0[i].z *= sc0; o0[i].w *= sc0;
            o1[i].x *= sc1; o1[i].y *= sc1; o1[i].z *= sc1; o1[i].w *= sc1;
        }

        // ---- accumulate pass: O += exp(s - m) * xi_p ----
#pragma unroll 1
        for (int p = 0; p < KP; p++) {
            float w0 = __expf(s0[p] - m0);
            float w1 = __expf(s1[p] - m1);
            l0 += w0; l1 += w1;
            const float4* xr = (const float4*)&xs[p * DIM];
#pragma unroll
            for (int i = 0; i < 8; i++) {
                float4 v = xr[lane + 32 * i];
                o0[i].x += w0 * v.x; o0[i].y += w0 * v.y;
                o0[i].z += w0 * v.z; o0[i].w += w0 * v.w;
                o1[i].x += w1 * v.x; o1[i].y += w1 * v.y;
                o1[i].z += w1 * v.z; o1[i].w += w1 * v.w;
            }
        }
    }

    const float inv0 = 1.f / l0, inv1 = 1.f / l1;
#pragma unroll
    for (int i = 0; i < 8; i++) {
        float4 r0 = make_float4(o0[i].x * inv0, o0[i].y * inv0, o0[i].z * inv0, o0[i].w * inv0);
        float4 r1 = make_float4(o1[i].x * inv1, o1[i].y * inv1, o1[i].z * inv1, o1[i].w * inv1);
        *(float4*)&out[row0 * DIM + 4 * lane + 128 * i] = r0;
        *(float4*)&out[row1 * DIM + 4 * lane + 128 * i] = r1;
    }
}

// =============================================================================
// launch
// =============================================================================
extern "C" void kernel_launch(void* const* d_in, const int* in_sizes, int n_in,
                              void* d_out, int out_size) {
    const float* x    = (const float*)d_in[0];
    const float* wq   = (const float*)d_in[1];
    const float* xi   = (const float*)d_in[2];
    const float* beta = (const float*)d_in[3];
    float* out = (float*)d_out;

    dim3 g1(DIM / 128, NROWS / 128);  // (8, 64)
    qgemm_kernel<<<g1, 256>>>(x, wq);

    const int smem2 = KP * DIM * sizeof(float);  // 64 KB
    cudaFuncSetAttribute(hopfield_attn_kernel,
                         cudaFuncAttributeMaxDynamicSharedMemorySize, smem2);
    hopfield_attn_kernel<<<NROWS / ROWS_PER_BLK, 256, smem2>>>(xi, beta, out);
}

// round 5
// speedup vs baseline: 15.9249x; 15.9140x over previous
#include <cuda_runtime.h>
#include <cuda_bf16.h>
#include <stdint.h>
#include <math.h>

#define DIM   1024
#define NPAT  8192
#define NROWS 8192

__device__ __nv_bfloat16 g_xb  [(size_t)NROWS * DIM];
__device__ __nv_bfloat16 g_wqb [(size_t)DIM * DIM];
__device__ __nv_bfloat16 g_xib [(size_t)NPAT * DIM];
__device__ __nv_bfloat16 g_xitb[(size_t)DIM * NPAT];
__device__ __nv_bfloat16 g_qb  [(size_t)NROWS * DIM];
__device__ __nv_bfloat16 g_p   [(size_t)NROWS * NPAT];
__device__ float g_rowsum[NROWS];
__device__ float g_colsum[DIM];

__device__ __forceinline__ uint32_t smem_u32(const void* p) {
    uint32_t a;
    asm("{ .reg .u64 t; cvta.to.shared.u64 t, %1; cvt.u32.u64 %0, t; }" : "=r"(a) : "l"(p));
    return a;
}
__device__ __forceinline__ uint32_t sw128(uint32_t o) { return o ^ ((o >> 3) & 0x70); }

#define LDMX4(r, a)                                                               \
    asm volatile("ldmatrix.sync.aligned.m8n8.x4.shared.b16 {%0,%1,%2,%3}, [%4];"  \
        : "=r"((r)[0]), "=r"((r)[1]), "=r"((r)[2]), "=r"((r)[3]) : "r"(a))

#define MMA16816(d, a, b0, b1)                                                    \
    asm volatile("mma.sync.aligned.m16n8k16.row.col.f32.bf16.bf16.f32 "           \
        "{%0,%1,%2,%3}, {%4,%5,%6,%7}, {%8,%9}, {%0,%1,%2,%3};"                   \
        : "+f"((d)[0]), "+f"((d)[1]), "+f"((d)[2]), "+f"((d)[3])                  \
        : "r"((a)[0]), "r"((a)[1]), "r"((a)[2]), "r"((a)[3]), "r"(b0), "r"(b1))

#define CP_ASYNC(s, g) \
    asm volatile("cp.async.cg.shared.global [%0], [%1], 16;" :: "r"(s), "l"(g))
#define CP_COMMIT() asm volatile("cp.async.commit_group;")
#define CP_WAIT(n)  asm volatile("cp.async.wait_group %0;" :: "n"(n))

// ---------------- prep kernels ----------------
__global__ void zero_kernel() {
    int i = blockIdx.x * blockDim.x + threadIdx.x;
    if (i < NROWS) g_rowsum[i] = 0.f;
    if (i < DIM)   g_colsum[i] = 0.f;
}
__global__ void cvt_kernel(const float4* __restrict__ src, __nv_bfloat162* __restrict__ dst, int n4) {
    int i = blockIdx.x * blockDim.x + threadIdx.x;
    if (i < n4) {
        float4 v = src[i];
        dst[2 * i]     = __floats2bfloat162_rn(v.x, v.y);
        dst[2 * i + 1] = __floats2bfloat162_rn(v.z, v.w);
    }
}
__global__ void transpose_kernel(const float* __restrict__ xi) {
    __shared__ __nv_bfloat16 t[32][33];
    int p0 = blockIdx.x * 32, d0 = blockIdx.y * 32;
    int tx = threadIdx.x, ty = threadIdx.y;
#pragma unroll
    for (int i = 0; i < 4; i++)
        t[ty + 8 * i][tx] = __float2bfloat16(xi[(size_t)(p0 + ty + 8 * i) * DIM + d0 + tx]);
    __syncthreads();
#pragma unroll
    for (int i = 0; i < 4; i++)
        g_xitb[(size_t)(d0 + ty + 8 * i) * NPAT + p0 + tx] = t[tx][ty + 8 * i];
}
__global__ void colsum_kernel(const float* __restrict__ xi) {
    int t = threadIdx.x;
    int r0 = blockIdx.x * 128;
    float4 a = make_float4(0.f, 0.f, 0.f, 0.f);
    for (int r = 0; r < 128; r++) {
        float4 v = ((const float4*)xi)[(size_t)(r0 + r) * (DIM / 4) + t];
        a.x += v.x; a.y += v.y; a.z += v.z; a.w += v.w;
    }
    atomicAdd(&g_colsum[4 * t + 0], a.x);
    atomicAdd(&g_colsum[4 * t + 1], a.y);
    atomicAdd(&g_colsum[4 * t + 2], a.z);
    atomicAdd(&g_colsum[4 * t + 3], a.w);
}

// =============================================================================
// bf16 HMMA GEMM: C[128x128] = A[128xK] * B[128xK]^T  (both row-major, K contig)
// 256 threads = 8 warps (4m x 2n), warp tile 32x64, mma.m16n8k16, fp32 accum.
// 3-stage cp.async pipeline, BK=64, SW128-swizzled smem (16KB A + 16KB B)/stage.
// EPI 0: store C->bf16 (g_qb). EPI 1: P'=exp(beta*C)-1 ->g_p + rowsum atomics.
// EPI 2: out = (C + colsum)/rowsum (fp32).
// =============================================================================
#define STAGES 3
#define STAGE_BYTES 32768
#define DSMEM (STAGES * STAGE_BYTES)

__device__ __forceinline__ void issue_stage(uint32_t sdst,
        const __nv_bfloat16* __restrict__ Ag, const __nv_bfloat16* __restrict__ Bg,
        int lda, int ldb, int bm, int bn, int k0, int tid) {
#pragma unroll
    for (int t = 0; t < 4; t++) {
        int id = tid + t * 256, row = id >> 3, c = id & 7;
        const void* g = Ag + (size_t)(bm + row) * lda + k0 + c * 8;
        CP_ASYNC(sdst + sw128(row * 128 + c * 16), g);
    }
#pragma unroll
    for (int t = 0; t < 4; t++) {
        int id = tid + t * 256, row = id >> 3, c = id & 7;
        const void* g = Bg + (size_t)(bn + row) * ldb + k0 + c * 8;
        CP_ASYNC(sdst + 16384 + sw128(row * 128 + c * 16), g);
    }
}

template <int EPI>
__global__ __launch_bounds__(256, 1) void hgemm(
        const __nv_bfloat16* __restrict__ A, const __nv_bfloat16* __restrict__ B,
        int lda, int ldb, int nk,
        const float* __restrict__ beta_ptr, float* __restrict__ outp) {
    extern __shared__ char sm[];
    const uint32_t sb = smem_u32(sm);
    const int tid = threadIdx.x, lane = tid & 31, w = tid >> 5;
    const int wm = w & 3, wn = w >> 2;
    const int bm = blockIdx.y * 128, bn = blockIdx.x * 128;

    float acc[2][8][4];
#pragma unroll
    for (int mt = 0; mt < 2; mt++)
#pragma unroll
        for (int nt = 0; nt < 8; nt++)
#pragma unroll
            for (int j = 0; j < 4; j++) acc[mt][nt][j] = 0.f;

    issue_stage(sb, A, B, lda, ldb, bm, bn, 0, tid);  CP_COMMIT();
    issue_stage(sb + STAGE_BYTES, A, B, lda, ldb, bm, bn, 64, tid);  CP_COMMIT();

    // precomputed (non-swizzled) lane offsets
    const uint32_t abase0 = (wm * 32 + (lane & 15)) * 128 + (lane >> 4) * 16;
    const uint32_t bbase0 = (wn * 64 + ((lane >> 4) & 1) * 8 + (lane & 7)) * 128 +
                            ((lane >> 3) & 1) * 16;

    for (int i = 0; i < nk; i++) {
        if (i == nk - 1) { CP_WAIT(0); } else { CP_WAIT(1); }
        __syncthreads();
        if (i + 2 < nk) {
            issue_stage(sb + ((i + 2) % STAGES) * STAGE_BYTES, A, B, lda, ldb, bm, bn,
                        (i + 2) * 64, tid);
            CP_COMMIT();
        }
        const uint32_t sA = sb + (i % STAGES) * STAGE_BYTES;
        const uint32_t sB = sA + 16384;
#pragma unroll
        for (int ks = 0; ks < 4; ks++) {
            uint32_t a[2][4], b[4][4];
#pragma unroll
            for (int mt = 0; mt < 2; mt++)
                LDMX4(a[mt], sA + sw128(abase0 + mt * 16 * 128 + ks * 32));
#pragma unroll
            for (int nt2 = 0; nt2 < 4; nt2++)
                LDMX4(b[nt2], sB + sw128(bbase0 + nt2 * 16 * 128 + ks * 32));
#pragma unroll
            for (int mt = 0; mt < 2; mt++)
#pragma unroll
                for (int nt = 0; nt < 8; nt++)
                    MMA16816(acc[mt][nt], a[mt], b[nt >> 1][(nt & 1) * 2],
                             b[nt >> 1][(nt & 1) * 2 + 1]);
        }
        __syncthreads();
    }

    // ------------------------------ epilogue ------------------------------
    const int rbase   = bm + wm * 32 + (lane >> 2);
    const int colbase = bn + wn * 64 + (lane & 3) * 2;

    if constexpr (EPI == 0) {
#pragma unroll
        for (int mt = 0; mt < 2; mt++)
#pragma unroll
            for (int nt = 0; nt < 8; nt++) {
                int col = colbase + nt * 8;
                int rA = rbase + mt * 16, rB = rA + 8;
                *(__nv_bfloat162*)&g_qb[(size_t)rA * DIM + col] =
                    __floats2bfloat162_rn(acc[mt][nt][0], acc[mt][nt][1]);
                *(__nv_bfloat162*)&g_qb[(size_t)rB * DIM + col] =
                    __floats2bfloat162_rn(acc[mt][nt][2], acc[mt][nt][3]);
            }
    } else if constexpr (EPI == 1) {
        const float beta = __ldg(beta_ptr);
        float rs[2][2] = {{0.f, 0.f}, {0.f, 0.f}};
#pragma unroll
        for (int mt = 0; mt < 2; mt++)
#pragma unroll
            for (int nt = 0; nt < 8; nt++) {
                int col = colbase + nt * 8;
                int rA = rbase + mt * 16, rB = rA + 8;
                float e0 = __expf(beta * acc[mt][nt][0]);
                float e1 = __expf(beta * acc[mt][nt][1]);
                float e2 = __expf(beta * acc[mt][nt][2]);
                float e3 = __expf(beta * acc[mt][nt][3]);
                rs[mt][0] += e0 + e1;
                rs[mt][1] += e2 + e3;
                *(__nv_bfloat162*)&g_p[(size_t)rA * NPAT + col] =
                    __floats2bfloat162_rn(e0 - 1.f, e1 - 1.f);
                *(__nv_bfloat162*)&g_p[(size_t)rB * NPAT + col] =
                    __floats2bfloat162_rn(e2 - 1.f, e3 - 1.f);
            }
#pragma unroll
        for (int mt = 0; mt < 2; mt++)
#pragma unroll
            for (int h = 0; h < 2; h++) {
                float v = rs[mt][h];
                v += __shfl_xor_sync(0xffffffffu, v, 1);
                v += __shfl_xor_sync(0xffffffffu, v, 2);
                if ((lane & 3) == 0)
                    atomicAdd(&g_rowsum[rbase + mt * 16 + h * 8], v);
            }
    } else {
        float inv[2][2];
#pragma unroll
        for (int mt = 0; mt < 2; mt++)
#pragma unroll
            for (int h = 0; h < 2; h++)
                inv[mt][h] = 1.f / g_rowsum[rbase + mt * 16 + h * 8];
#pragma unroll
        for (int mt = 0; mt < 2; mt++)
#pragma unroll
            for (int nt = 0; nt < 8; nt++) {
                int col = colbase + nt * 8;
                int rA = rbase + mt * 16, rB = rA + 8;
                float cs0 = g_colsum[col], cs1 = g_colsum[col + 1];
                *(float2*)&outp[(size_t)rA * DIM + col] =
                    make_float2((acc[mt][nt][0] + cs0) * inv[mt][0],
                                (acc[mt][nt][1] + cs1) * inv[mt][0]);
                *(float2*)&outp[(size_t)rB * DIM + col] =
                    make_float2((acc[mt][nt][2] + cs0) * inv[mt][1],
                                (acc[mt][nt][3] + cs1) * inv[mt][1]);
            }
    }
}

// ---------------- host ----------------
extern "C" void kernel_launch(void* const* d_in, const int* in_sizes, int n_in,
                              void* d_out, int out_size) {
    const float* x    = (const float*)d_in[0];
    const float* wq   = (const float*)d_in[1];
    const float* xi   = (const float*)d_in[2];
    const float* beta = (const float*)d_in[3];
    float* out = (float*)d_out;

    void *p_xb, *p_wqb, *p_xib, *p_xitb, *p_qb, *p_p;
    cudaGetSymbolAddress(&p_xb, g_xb);
    cudaGetSymbolAddress(&p_wqb, g_wqb);
    cudaGetSymbolAddress(&p_xib, g_xib);
    cudaGetSymbolAddress(&p_xitb, g_xitb);
    cudaGetSymbolAddress(&p_qb, g_qb);
    cudaGetSymbolAddress(&p_p, g_p);

    static bool attr_done = false;
    if (!attr_done) {
        cudaFuncSetAttribute(hgemm<0>, cudaFuncAttributeMaxDynamicSharedMemorySize, DSMEM);
        cudaFuncSetAttribute(hgemm<1>, cudaFuncAttributeMaxDynamicSharedMemorySize, DSMEM);
        cudaFuncSetAttribute(hgemm<2>, cudaFuncAttributeMaxDynamicSharedMemorySize, DSMEM);
        attr_done = true;
    }

    cvt_kernel<<<(NROWS * DIM / 4 + 255) / 256, 256>>>((const float4*)x,  (__nv_bfloat162*)p_xb,  NROWS * DIM / 4);
    cvt_kernel<<<(DIM * DIM / 4 + 255) / 256, 256>>>((const float4*)wq, (__nv_bfloat162*)p_wqb, DIM * DIM / 4);
    cvt_kernel<<<(NPAT * DIM / 4 + 255) / 256, 256>>>((const float4*)xi, (__nv_bfloat162*)p_xib, NPAT * DIM / 4);
    transpose_kernel<<<dim3(NPAT / 32, DIM / 32), dim3(32, 8)>>>(xi);
    zero_kernel<<<(NROWS + 255) / 256, 256>>>();
    colsum_kernel<<<NPAT / 128, 256>>>(xi);

    // q = x * wq^T
    hgemm<0><<<dim3(DIM / 128, NROWS / 128), 256, DSMEM>>>(
        (const __nv_bfloat16*)p_xb, (const __nv_bfloat16*)p_wqb, DIM, DIM, DIM / 64, beta, out);
    // P' = exp(beta * q * xi^T) - 1, rowsum
    hgemm<1><<<dim3(NPAT / 128, NROWS / 128), 256, DSMEM>>>(
        (const __nv_bfloat16*)p_qb, (const __nv_bfloat16*)p_xib, DIM, DIM, DIM / 64, beta, out);
    // out = (P' * xi + colsum) / rowsum
    hgemm<2><<<dim3(DIM / 128, NROWS / 128), 256, DSMEM>>>(
        (const __nv_bfloat16*)p_p, (const __nv_bfloat16*)p_xitb, NPAT, NPAT, NPAT / 64, beta, out);
}